// round 7
// baseline (speedup 1.0000x reference)
#include <cuda_runtime.h>

#define D_    128
#define ED_   16
#define N_MAX 100000
#define L_MAX 5

// per-layer per-node projections, layout [layer][node][16]
__device__ float g_p[(size_t)L_MAX * N_MAX * ED_];
__device__ float g_q[(size_t)L_MAX * N_MAX * ED_];

// edge-MLP weights packed as float pairs for fma.rn.f32x2
__constant__ __align__(16) ulonglong2 cWC[L_MAX][64];
__constant__ __align__(16) ulonglong2 cW2[L_MAX][64];
__constant__ __align__(16) unsigned long long cB1[L_MAX][8];
__constant__ __align__(16) unsigned long long cB2[L_MAX][8];

// ---- f32x2 packed helpers ----
__device__ __forceinline__ unsigned long long pk2(float a) {
    unsigned long long r; asm("mov.b64 %0, {%1, %1};" : "=l"(r) : "f"(a)); return r;
}
__device__ __forceinline__ float2 up2(unsigned long long v) {
    float2 r; asm("mov.b64 {%0, %1}, %2;" : "=f"(r.x), "=f"(r.y) : "l"(v)); return r;
}
__device__ __forceinline__ unsigned long long fma2(unsigned long long a,
                                                   unsigned long long b,
                                                   unsigned long long c) {
    unsigned long long d;
    asm("fma.rn.f32x2 %0, %1, %2, %3;" : "=l"(d) : "l"(a), "l"(b), "l"(c));
    return d;
}
__device__ __forceinline__ unsigned long long add2(unsigned long long a,
                                                   unsigned long long b) {
    unsigned long long d;
    asm("add.rn.f32x2 %0, %1, %2;" : "=l"(d) : "l"(a), "l"(b));
    return d;
}

// ---------------------------------------------------------------------------
// All L layers of LayerNorm + both 128->16 projections. 8 rows per warp,
// rows live in registers across layers; 24 warps/SM for latency hiding.
// ---------------------------------------------------------------------------
__global__ __launch_bounds__(768) void ln_all_kernel(
    const float* __restrict__ s_in, float* __restrict__ s_out,
    const float* __restrict__ lnw, const float* __restrict__ lnb,
    const float* __restrict__ eW1 /* [L,272,16] */, int n, int L)
{
    extern __shared__ __align__(16) float sm[];
    float* wT     = sm;                       // [5][32*132] transposed Wa|Wb
    float* sLn    = wT + L_MAX * 4224;        // [5][256] lnw|lnb
    float* rowbuf = sLn + L_MAX * 256;        // [24 warps][8*128]

    for (int l = 0; l < L; ++l) {
        const float* w1 = eW1 + (size_t)l * 272 * 16;
        float* wTl = wT + l * 4224;
        for (int idx = threadIdx.x; idx < 2048; idx += 768) {
            int k = idx >> 4, j = idx & 15;
            wTl[j * 132 + k]        = w1[idx];          // Wa
            wTl[(16 + j) * 132 + k] = w1[2048 + idx];   // Wb
        }
        for (int idx = threadIdx.x; idx < 128; idx += 768) {
            sLn[l * 256 + idx]       = lnw[l * 128 + idx];
            sLn[l * 256 + 128 + idx] = lnb[l * 128 + idx];
        }
    }
    __syncthreads();

    int warp = threadIdx.x >> 5, lane = threadIdx.x & 31;
    float* rb = rowbuf + warp * 1024;
    int j = lane & 15;
    int rowsel = (lane < 16) ? 0 : 16;
    float* dstbase = (lane < 16) ? g_p : g_q;

    int stride = gridDim.x * 24 * 8;
    for (int row0 = (blockIdx.x * 24 + warp) * 8; row0 < n; row0 += stride) {
        if (row0 + 8 <= n) {
            // ---------------- full-tile fast path ----------------
            float4 v[8];
            #pragma unroll
            for (int r = 0; r < 8; ++r)
                v[r] = reinterpret_cast<const float4*>(s_in)[(size_t)(row0 + r) * 32 + lane];

            for (int l = 0; l < L; ++l) {
                const float4* lnp = reinterpret_cast<const float4*>(sLn + l * 256);
                float4 wv = lnp[lane], bv = lnp[32 + lane];

                float s1[8], s2[8];
                #pragma unroll
                for (int r = 0; r < 8; ++r) {
                    s1[r] = (v[r].x + v[r].y) + (v[r].z + v[r].w);
                    s2[r] = fmaf(v[r].x, v[r].x,
                            fmaf(v[r].y, v[r].y,
                            fmaf(v[r].z, v[r].z, v[r].w * v[r].w)));
                }
                #pragma unroll
                for (int o = 16; o; o >>= 1) {
                    #pragma unroll
                    for (int r = 0; r < 8; ++r) {
                        s1[r] += __shfl_xor_sync(0xffffffffu, s1[r], o);
                        s2[r] += __shfl_xor_sync(0xffffffffu, s2[r], o);
                    }
                }
                #pragma unroll
                for (int r = 0; r < 8; ++r) {
                    float mu = s1[r] * 0.0078125f;
                    float rstd = rsqrtf(fmaf(s2[r], 0.0078125f, -mu * mu) + 1e-5f);
                    v[r].x = (v[r].x - mu) * rstd * wv.x + bv.x;
                    v[r].y = (v[r].y - mu) * rstd * wv.y + bv.y;
                    v[r].z = (v[r].z - mu) * rstd * wv.z + bv.z;
                    v[r].w = (v[r].w - mu) * rstd * wv.w + bv.w;
                    reinterpret_cast<float4*>(rb + r * 128)[lane] = v[r];
                }
                __syncwarp();

                const ulonglong2* wrow =
                    reinterpret_cast<const ulonglong2*>(wT + l * 4224 + (rowsel + j) * 132);
                unsigned long long acc[8] = {0,0,0,0,0,0,0,0};
                #pragma unroll
                for (int c = 0; c < 32; ++c) {
                    ulonglong2 wv2 = wrow[c];
                    #pragma unroll
                    for (int r = 0; r < 8; ++r) {
                        ulonglong2 rv = reinterpret_cast<const ulonglong2*>(rb + r * 128)[c];
                        acc[r] = fma2(rv.x, wv2.x, acc[r]);
                        acc[r] = fma2(rv.y, wv2.y, acc[r]);
                    }
                }
                #pragma unroll
                for (int r = 0; r < 8; ++r) {
                    float2 a = up2(acc[r]);
                    dstbase[((size_t)l * N_MAX + (row0 + r)) * 16 + j] = a.x + a.y;
                }
                __syncwarp();
            }

            #pragma unroll
            for (int r = 0; r < 8; ++r)
                reinterpret_cast<float4*>(s_out)[(size_t)(row0 + r) * 32 + lane] = v[r];
        } else {
            // ---------------- tail path (rare) ----------------
            int nr = n - row0;
            for (int r = 0; r < nr; ++r) {
                float4 v = reinterpret_cast<const float4*>(s_in)[(size_t)(row0 + r) * 32 + lane];
                for (int l = 0; l < L; ++l) {
                    const float4* lnp = reinterpret_cast<const float4*>(sLn + l * 256);
                    float4 wv = lnp[lane], bv = lnp[32 + lane];
                    float s1 = (v.x + v.y) + (v.z + v.w);
                    float s2 = fmaf(v.x, v.x, fmaf(v.y, v.y, fmaf(v.z, v.z, v.w * v.w)));
                    #pragma unroll
                    for (int o = 16; o; o >>= 1) {
                        s1 += __shfl_xor_sync(0xffffffffu, s1, o);
                        s2 += __shfl_xor_sync(0xffffffffu, s2, o);
                    }
                    float mu = s1 * 0.0078125f;
                    float rstd = rsqrtf(fmaf(s2, 0.0078125f, -mu * mu) + 1e-5f);
                    v.x = (v.x - mu) * rstd * wv.x + bv.x;
                    v.y = (v.y - mu) * rstd * wv.y + bv.y;
                    v.z = (v.z - mu) * rstd * wv.z + bv.z;
                    v.w = (v.w - mu) * rstd * wv.w + bv.w;
                    reinterpret_cast<float4*>(rb)[lane] = v;
                    __syncwarp();
                    const ulonglong2* wrow =
                        reinterpret_cast<const ulonglong2*>(wT + l * 4224 + (rowsel + j) * 132);
                    unsigned long long a0 = 0ull, a1 = 0ull;
                    #pragma unroll
                    for (int c = 0; c < 32; c += 2) {
                        ulonglong2 w0 = wrow[c], w1v = wrow[c + 1];
                        ulonglong2 r0 = reinterpret_cast<const ulonglong2*>(rb)[c];
                        ulonglong2 r1 = reinterpret_cast<const ulonglong2*>(rb)[c + 1];
                        a0 = fma2(r0.x, w0.x,  a0);
                        a0 = fma2(r0.y, w0.y,  a0);
                        a1 = fma2(r1.x, w1v.x, a1);
                        a1 = fma2(r1.y, w1v.y, a1);
                    }
                    float2 f0 = up2(a0), f1 = up2(a1);
                    dstbase[((size_t)l * N_MAX + (row0 + r)) * 16 + j] =
                        (f0.x + f0.y) + (f1.x + f1.y);
                    __syncwarp();
                }
                reinterpret_cast<float4*>(s_out)[(size_t)(row0 + r) * 32 + lane] = v;
            }
        }
    }
}

// ---------------------------------------------------------------------------
// One thread per edge, one layer per launch. Gathers are COOPERATIVE:
// 4 lanes fetch one 64B p/q row (few L1 lines per instruction), staged in
// smem (80B row stride -> conflict degree 4), then each thread runs the MLP
// on its own edge with constant-port weights.
// ---------------------------------------------------------------------------
#define ROWSTRIDE 20   // floats per staged row (16 data + 4 pad), 80B
__global__ __launch_bounds__(256) void edge_kernel(
    const int* __restrict__ src, const int* __restrict__ dst,
    const float* __restrict__ ea_in, float* __restrict__ ea_out,
    int layer, int e_total)
{
    __shared__ __align__(16) float sRow[512 * ROWSTRIDE]; // 256 P rows | 256 Q rows
    __shared__ int sIdx[512];                             // src[0..255] | dst[0..255]

    int tid = threadIdx.x;
    int e = blockIdx.x * 256 + tid;
    int e_clamped = (e < e_total) ? e : (e_total - 1);

    sIdx[tid]       = src[e_clamped];
    sIdx[256 + tid] = dst[e_clamped];

    // own edge_attr load (independent of gather)
    float ea[16];
    {
        const float4* EA = reinterpret_cast<const float4*>(ea_in + (size_t)e_clamped * 16);
        #pragma unroll
        for (int c = 0; c < 4; ++c) {
            float4 t = EA[c];
            ea[4*c] = t.x; ea[4*c+1] = t.y; ea[4*c+2] = t.z; ea[4*c+3] = t.w;
        }
    }
    __syncthreads();

    // cooperative gather: 512 rows * 4 float4-slots = 2048 slots, 8 per thread
    const float* gbase[2] = { g_p + (size_t)layer * N_MAX * 16,
                              g_q + (size_t)layer * N_MAX * 16 };
    #pragma unroll
    for (int it = 0; it < 8; ++it) {
        int slot = it * 256 + tid;
        int row  = slot >> 2;          // 0..511
        int part = slot & 3;
        int node = sIdx[row];
        const float4* srcp = reinterpret_cast<const float4*>(
            gbase[row >> 8] + (size_t)node * 16) + part;
        float4 val = *srcp;
        *reinterpret_cast<float4*>(sRow + row * ROWSTRIDE + part * 4) = val;
    }
    __syncthreads();

    if (e >= e_total) return;

    const ulonglong2* P = reinterpret_cast<const ulonglong2*>(sRow + tid * ROWSTRIDE);
    const ulonglong2* Q = reinterpret_cast<const ulonglong2*>(sRow + (256 + tid) * ROWSTRIDE);

    unsigned long long h[8];
    #pragma unroll
    for (int i = 0; i < 2; ++i) {
        ulonglong2 pv = P[i], qv = Q[i];
        h[2*i+0] = add2(add2(pv.x, qv.x), cB1[layer][2*i+0]);
        h[2*i+1] = add2(add2(pv.y, qv.y), cB1[layer][2*i+1]);
    }
    #pragma unroll
    for (int i = 2; i < 4; ++i) {
        ulonglong2 pv = P[i], qv = Q[i];
        h[2*i+0] = add2(add2(pv.x, qv.x), cB1[layer][2*i+0]);
        h[2*i+1] = add2(add2(pv.y, qv.y), cB1[layer][2*i+1]);
    }

    #pragma unroll
    for (int k = 0; k < 16; ++k) {
        unsigned long long ek = pk2(ea[k]);
        ulonglong2 w0 = cWC[layer][k*4+0], w1 = cWC[layer][k*4+1];
        ulonglong2 w2v = cWC[layer][k*4+2], w3 = cWC[layer][k*4+3];
        h[0] = fma2(ek, w0.x,  h[0]);  h[1] = fma2(ek, w0.y,  h[1]);
        h[2] = fma2(ek, w1.x,  h[2]);  h[3] = fma2(ek, w1.y,  h[3]);
        h[4] = fma2(ek, w2v.x, h[4]);  h[5] = fma2(ek, w2v.y, h[5]);
        h[6] = fma2(ek, w3.x,  h[6]);  h[7] = fma2(ek, w3.y,  h[7]);
    }

    float z[16];
    #pragma unroll
    for (int i = 0; i < 8; ++i) {
        float2 hv = up2(h[i]);
        z[2*i]   = __fdividef(hv.x, 1.0f + __expf(-hv.x));   // silu
        z[2*i+1] = __fdividef(hv.y, 1.0f + __expf(-hv.y));
    }

    unsigned long long o[8];
    #pragma unroll
    for (int i = 0; i < 8; ++i) o[i] = cB2[layer][i];
    #pragma unroll
    for (int k = 0; k < 16; ++k) {
        unsigned long long zk = pk2(z[k]);
        ulonglong2 w0 = cW2[layer][k*4+0], w1 = cW2[layer][k*4+1];
        ulonglong2 w2v = cW2[layer][k*4+2], w3 = cW2[layer][k*4+3];
        o[0] = fma2(zk, w0.x,  o[0]);  o[1] = fma2(zk, w0.y,  o[1]);
        o[2] = fma2(zk, w1.x,  o[2]);  o[3] = fma2(zk, w1.y,  o[3]);
        o[4] = fma2(zk, w2v.x, o[4]);  o[5] = fma2(zk, w2v.y, o[5]);
        o[6] = fma2(zk, w3.x,  o[6]);  o[7] = fma2(zk, w3.y,  o[7]);
    }

    ulonglong2* OUT = reinterpret_cast<ulonglong2*>(ea_out + (size_t)e * 16);
    #pragma unroll
    for (int i = 0; i < 4; ++i)
        OUT[i] = make_ulonglong2(o[2*i], o[2*i+1]);
}

extern "C" void kernel_launch(void* const* d_in, const int* in_sizes, int n_in,
                              void* d_out, int out_size)
{
    const float* s0   = (const float*)d_in[0];       // [N,128]
    const int*   ei   = (const int*)d_in[1];         // [2,E] int32
    const float* ea0  = (const float*)d_in[2];       // [E,16]
    const float* lnw  = (const float*)d_in[4];       // [L,128]
    const float* lnb  = (const float*)d_in[5];       // [L,128]
    const float* eW1  = (const float*)d_in[6];       // [L,272,16]
    const float* eb1  = (const float*)d_in[7];       // [L,16]
    const float* eW2  = (const float*)d_in[8];       // [L,16,16]
    const float* eb2  = (const float*)d_in[9];       // [L,16]
    // batch / nW1 / nb1 / nW2 / nb2 are dead in the reference dataflow

    int n = in_sizes[0] / D_;
    int e = in_sizes[2] / ED_;
    int L = in_sizes[4] / D_;

    float* out    = (float*)d_out;
    float* s_buf  = out;                      // final s
    float* ea_buf = out + (size_t)n * D_;     // final edge_attr

    const int* src = ei;
    const int* dst = ei + e;

    // stage edge-MLP weights into constant memory (capturable D2D copies)
    void *pWC, *pW2, *pB1, *pB2;
    cudaGetSymbolAddress(&pWC, cWC);
    cudaGetSymbolAddress(&pW2, cW2);
    cudaGetSymbolAddress(&pB1, cB1);
    cudaGetSymbolAddress(&pB2, cB2);
    cudaMemcpy2DAsync(pWC, 1024, eW1 + 256 * 16, 272 * 16 * 4, 1024, L,
                      cudaMemcpyDeviceToDevice);
    cudaMemcpyAsync(pW2, eW2, (size_t)L * 256 * 4, cudaMemcpyDeviceToDevice);
    cudaMemcpyAsync(pB1, eb1, (size_t)L * 16 * 4, cudaMemcpyDeviceToDevice);
    cudaMemcpyAsync(pB2, eb2, (size_t)L * 16 * 4, cudaMemcpyDeviceToDevice);

    size_t shmem = (size_t)(L_MAX * 4224 + L_MAX * 256 + 24 * 1024) * 4;
    cudaFuncSetAttribute(ln_all_kernel,
                         cudaFuncAttributeMaxDynamicSharedMemorySize, (int)shmem);

    ln_all_kernel<<<148, 768, shmem>>>(s0, s_buf, lnw, lnb, eW1, n, L);

    int edge_blocks = (e + 255) / 256;
    for (int i = 0; i < L; ++i)
        edge_kernel<<<edge_blocks, 256>>>(
            src, dst,
            (i == 0) ? ea0 : ea_buf, ea_buf,
            i, e);
}

// round 8
// speedup vs baseline: 1.0315x; 1.0315x over previous
#include <cuda_runtime.h>

#define D_    128
#define ED_   16
#define N_MAX 100000
#define L_MAX 5

// per-layer per-node projections, layout [layer][node][16] (64B rows, aligned)
__device__ __align__(128) float g_p[(size_t)L_MAX * N_MAX * ED_];
__device__ __align__(128) float g_q[(size_t)L_MAX * N_MAX * ED_];

// edge-MLP weights packed as float pairs for fma.rn.f32x2
__constant__ __align__(16) ulonglong2 cWC[L_MAX][64];
__constant__ __align__(16) ulonglong2 cW2[L_MAX][64];
__constant__ __align__(16) unsigned long long cB1[L_MAX][8];
__constant__ __align__(16) unsigned long long cB2[L_MAX][8];

// ---- f32x2 packed helpers ----
__device__ __forceinline__ unsigned long long pk2(float a) {
    unsigned long long r; asm("mov.b64 %0, {%1, %1};" : "=l"(r) : "f"(a)); return r;
}
__device__ __forceinline__ float2 up2(unsigned long long v) {
    float2 r; asm("mov.b64 {%0, %1}, %2;" : "=f"(r.x), "=f"(r.y) : "l"(v)); return r;
}
__device__ __forceinline__ unsigned long long fma2(unsigned long long a,
                                                   unsigned long long b,
                                                   unsigned long long c) {
    unsigned long long d;
    asm("fma.rn.f32x2 %0, %1, %2, %3;" : "=l"(d) : "l"(a), "l"(b), "l"(c));
    return d;
}
__device__ __forceinline__ unsigned long long add2(unsigned long long a,
                                                   unsigned long long b) {
    unsigned long long d;
    asm("add.rn.f32x2 %0, %1, %2;" : "=l"(d) : "l"(a), "l"(b));
    return d;
}

// ---------------------------------------------------------------------------
// All L layers of LayerNorm + both 128->16 projections. 8 rows per warp,
// rows live in registers across layers.
// ---------------------------------------------------------------------------
__global__ __launch_bounds__(768) void ln_all_kernel(
    const float* __restrict__ s_in, float* __restrict__ s_out,
    const float* __restrict__ lnw, const float* __restrict__ lnb,
    const float* __restrict__ eW1 /* [L,272,16] */, int n, int L)
{
    extern __shared__ __align__(16) float sm[];
    float* wT     = sm;                       // [5][32*132] transposed Wa|Wb
    float* sLn    = wT + L_MAX * 4224;        // [5][256] lnw|lnb
    float* rowbuf = sLn + L_MAX * 256;        // [24 warps][8*128]

    for (int l = 0; l < L; ++l) {
        const float* w1 = eW1 + (size_t)l * 272 * 16;
        float* wTl = wT + l * 4224;
        for (int idx = threadIdx.x; idx < 2048; idx += 768) {
            int k = idx >> 4, j = idx & 15;
            wTl[j * 132 + k]        = w1[idx];          // Wa
            wTl[(16 + j) * 132 + k] = w1[2048 + idx];   // Wb
        }
        for (int idx = threadIdx.x; idx < 128; idx += 768) {
            sLn[l * 256 + idx]       = lnw[l * 128 + idx];
            sLn[l * 256 + 128 + idx] = lnb[l * 128 + idx];
        }
    }
    __syncthreads();

    int warp = threadIdx.x >> 5, lane = threadIdx.x & 31;
    float* rb = rowbuf + warp * 1024;
    int j = lane & 15;
    int rowsel = (lane < 16) ? 0 : 16;
    float* dstbase = (lane < 16) ? g_p : g_q;

    int stride = gridDim.x * 24 * 8;
    for (int row0 = (blockIdx.x * 24 + warp) * 8; row0 < n; row0 += stride) {
        if (row0 + 8 <= n) {
            float4 v[8];
            #pragma unroll
            for (int r = 0; r < 8; ++r)
                v[r] = reinterpret_cast<const float4*>(s_in)[(size_t)(row0 + r) * 32 + lane];

            for (int l = 0; l < L; ++l) {
                const float4* lnp = reinterpret_cast<const float4*>(sLn + l * 256);
                float4 wv = lnp[lane], bv = lnp[32 + lane];

                float s1[8], s2[8];
                #pragma unroll
                for (int r = 0; r < 8; ++r) {
                    s1[r] = (v[r].x + v[r].y) + (v[r].z + v[r].w);
                    s2[r] = fmaf(v[r].x, v[r].x,
                            fmaf(v[r].y, v[r].y,
                            fmaf(v[r].z, v[r].z, v[r].w * v[r].w)));
                }
                #pragma unroll
                for (int o = 16; o; o >>= 1) {
                    #pragma unroll
                    for (int r = 0; r < 8; ++r) {
                        s1[r] += __shfl_xor_sync(0xffffffffu, s1[r], o);
                        s2[r] += __shfl_xor_sync(0xffffffffu, s2[r], o);
                    }
                }
                #pragma unroll
                for (int r = 0; r < 8; ++r) {
                    float mu = s1[r] * 0.0078125f;
                    float rstd = rsqrtf(fmaf(s2[r], 0.0078125f, -mu * mu) + 1e-5f);
                    v[r].x = (v[r].x - mu) * rstd * wv.x + bv.x;
                    v[r].y = (v[r].y - mu) * rstd * wv.y + bv.y;
                    v[r].z = (v[r].z - mu) * rstd * wv.z + bv.z;
                    v[r].w = (v[r].w - mu) * rstd * wv.w + bv.w;
                    reinterpret_cast<float4*>(rb + r * 128)[lane] = v[r];
                }
                __syncwarp();

                const ulonglong2* wrow =
                    reinterpret_cast<const ulonglong2*>(wT + l * 4224 + (rowsel + j) * 132);
                unsigned long long acc[8] = {0,0,0,0,0,0,0,0};
                #pragma unroll
                for (int c = 0; c < 32; ++c) {
                    ulonglong2 wv2 = wrow[c];
                    #pragma unroll
                    for (int r = 0; r < 8; ++r) {
                        ulonglong2 rv = reinterpret_cast<const ulonglong2*>(rb + r * 128)[c];
                        acc[r] = fma2(rv.x, wv2.x, acc[r]);
                        acc[r] = fma2(rv.y, wv2.y, acc[r]);
                    }
                }
                #pragma unroll
                for (int r = 0; r < 8; ++r) {
                    float2 a = up2(acc[r]);
                    dstbase[((size_t)l * N_MAX + (row0 + r)) * 16 + j] = a.x + a.y;
                }
                __syncwarp();
            }

            #pragma unroll
            for (int r = 0; r < 8; ++r)
                reinterpret_cast<float4*>(s_out)[(size_t)(row0 + r) * 32 + lane] = v[r];
        } else {
            int nr = n - row0;
            for (int r = 0; r < nr; ++r) {
                float4 v = reinterpret_cast<const float4*>(s_in)[(size_t)(row0 + r) * 32 + lane];
                for (int l = 0; l < L; ++l) {
                    const float4* lnp = reinterpret_cast<const float4*>(sLn + l * 256);
                    float4 wv = lnp[lane], bv = lnp[32 + lane];
                    float s1 = (v.x + v.y) + (v.z + v.w);
                    float s2 = fmaf(v.x, v.x, fmaf(v.y, v.y, fmaf(v.z, v.z, v.w * v.w)));
                    #pragma unroll
                    for (int o = 16; o; o >>= 1) {
                        s1 += __shfl_xor_sync(0xffffffffu, s1, o);
                        s2 += __shfl_xor_sync(0xffffffffu, s2, o);
                    }
                    float mu = s1 * 0.0078125f;
                    float rstd = rsqrtf(fmaf(s2, 0.0078125f, -mu * mu) + 1e-5f);
                    v.x = (v.x - mu) * rstd * wv.x + bv.x;
                    v.y = (v.y - mu) * rstd * wv.y + bv.y;
                    v.z = (v.z - mu) * rstd * wv.z + bv.z;
                    v.w = (v.w - mu) * rstd * wv.w + bv.w;
                    reinterpret_cast<float4*>(rb)[lane] = v;
                    __syncwarp();
                    const ulonglong2* wrow =
                        reinterpret_cast<const ulonglong2*>(wT + l * 4224 + (rowsel + j) * 132);
                    unsigned long long a0 = 0ull, a1 = 0ull;
                    #pragma unroll
                    for (int c = 0; c < 32; c += 2) {
                        ulonglong2 w0 = wrow[c], w1v = wrow[c + 1];
                        ulonglong2 r0 = reinterpret_cast<const ulonglong2*>(rb)[c];
                        ulonglong2 r1 = reinterpret_cast<const ulonglong2*>(rb)[c + 1];
                        a0 = fma2(r0.x, w0.x,  a0);
                        a0 = fma2(r0.y, w0.y,  a0);
                        a1 = fma2(r1.x, w1v.x, a1);
                        a1 = fma2(r1.y, w1v.y, a1);
                    }
                    float2 f0 = up2(a0), f1 = up2(a1);
                    dstbase[((size_t)l * N_MAX + (row0 + r)) * 16 + j] =
                        (f0.x + f0.y) + (f1.x + f1.y);
                    __syncwarp();
                }
                reinterpret_cast<float4*>(s_out)[(size_t)(row0 + r) * 32 + lane] = v;
            }
        }
    }
}

// ---------------------------------------------------------------------------
// Edge MLP, one layer per launch. WARP-LOCAL cooperative gather:
// each warp owns 32 edges; 4 lanes fetch one 64B-aligned p/q row per LDG.128
// (≤8 lines/instruction instead of 32), staged in a per-warp smem tile,
// synced with __syncwarp only (no block barrier). MLP uses constant-port
// weights and packed f32x2 math.
// ---------------------------------------------------------------------------
#define RSTRIDE 20   // floats per staged row (16 data + 4 pad) -> 16B aligned
__global__ __launch_bounds__(256) void edge_kernel(
    const int* __restrict__ src, const int* __restrict__ dst,
    const float* __restrict__ ea_in, float* __restrict__ ea_out,
    int layer, int e_total)
{
    // 8 warps * 64 rows (32 P + 32 Q) * 20 floats = 40960 B
    __shared__ __align__(16) float sRow[8 * 64 * RSTRIDE];

    int warp = threadIdx.x >> 5, lane = threadIdx.x & 31;
    float* wbuf = sRow + warp * (64 * RSTRIDE);

    int e = blockIdx.x * 256 + warp * 32 + lane;
    int ec = (e < e_total) ? e : (e_total - 1);

    int si = src[ec], di = dst[ec];

    // own edge_attr (independent of gather latency)
    float ea[16];
    {
        const float4* EA = reinterpret_cast<const float4*>(ea_in + (size_t)ec * 16);
        #pragma unroll
        for (int c = 0; c < 4; ++c) {
            float4 t = EA[c];
            ea[4*c] = t.x; ea[4*c+1] = t.y; ea[4*c+2] = t.z; ea[4*c+3] = t.w;
        }
    }

    // warp-cooperative gather: 4 lanes per row
    const float* Pbase = g_p + (size_t)layer * N_MAX * 16;
    const float* Qbase = g_q + (size_t)layer * N_MAX * 16;
    int part = lane & 3;
    #pragma unroll
    for (int i = 0; i < 4; ++i) {
        int t  = i * 8 + (lane >> 2);                     // edge slot 0..31
        int ns = __shfl_sync(0xffffffffu, si, t);
        int nd = __shfl_sync(0xffffffffu, di, t);
        float4 pv = *(reinterpret_cast<const float4*>(Pbase + (size_t)ns * 16) + part);
        float4 qv = *(reinterpret_cast<const float4*>(Qbase + (size_t)nd * 16) + part);
        *reinterpret_cast<float4*>(wbuf + t * RSTRIDE + part * 4) = pv;
        *reinterpret_cast<float4*>(wbuf + (32 + t) * RSTRIDE + part * 4) = qv;
    }
    __syncwarp();

    if (e >= e_total) return;

    const ulonglong2* P = reinterpret_cast<const ulonglong2*>(wbuf + lane * RSTRIDE);
    const ulonglong2* Q = reinterpret_cast<const ulonglong2*>(wbuf + (32 + lane) * RSTRIDE);

    unsigned long long h[8];
    #pragma unroll
    for (int i = 0; i < 4; ++i) {
        ulonglong2 pv = P[i], qv = Q[i];
        h[2*i+0] = add2(add2(pv.x, qv.x), cB1[layer][2*i+0]);
        h[2*i+1] = add2(add2(pv.y, qv.y), cB1[layer][2*i+1]);
    }

    #pragma unroll
    for (int k = 0; k < 16; ++k) {
        unsigned long long ek = pk2(ea[k]);
        ulonglong2 w0 = cWC[layer][k*4+0], w1 = cWC[layer][k*4+1];
        ulonglong2 w2v = cWC[layer][k*4+2], w3 = cWC[layer][k*4+3];
        h[0] = fma2(ek, w0.x,  h[0]);  h[1] = fma2(ek, w0.y,  h[1]);
        h[2] = fma2(ek, w1.x,  h[2]);  h[3] = fma2(ek, w1.y,  h[3]);
        h[4] = fma2(ek, w2v.x, h[4]);  h[5] = fma2(ek, w2v.y, h[5]);
        h[6] = fma2(ek, w3.x,  h[6]);  h[7] = fma2(ek, w3.y,  h[7]);
    }

    float z[16];
    #pragma unroll
    for (int i = 0; i < 8; ++i) {
        float2 hv = up2(h[i]);
        z[2*i]   = __fdividef(hv.x, 1.0f + __expf(-hv.x));   // silu
        z[2*i+1] = __fdividef(hv.y, 1.0f + __expf(-hv.y));
    }

    unsigned long long o[8];
    #pragma unroll
    for (int i = 0; i < 8; ++i) o[i] = cB2[layer][i];
    #pragma unroll
    for (int k = 0; k < 16; ++k) {
        unsigned long long zk = pk2(z[k]);
        ulonglong2 w0 = cW2[layer][k*4+0], w1 = cW2[layer][k*4+1];
        ulonglong2 w2v = cW2[layer][k*4+2], w3 = cW2[layer][k*4+3];
        o[0] = fma2(zk, w0.x,  o[0]);  o[1] = fma2(zk, w0.y,  o[1]);
        o[2] = fma2(zk, w1.x,  o[2]);  o[3] = fma2(zk, w1.y,  o[3]);
        o[4] = fma2(zk, w2v.x, o[4]);  o[5] = fma2(zk, w2v.y, o[5]);
        o[6] = fma2(zk, w3.x,  o[6]);  o[7] = fma2(zk, w3.y,  o[7]);
    }

    ulonglong2* OUT = reinterpret_cast<ulonglong2*>(ea_out + (size_t)e * 16);
    #pragma unroll
    for (int i = 0; i < 4; ++i)
        OUT[i] = make_ulonglong2(o[2*i], o[2*i+1]);
}

extern "C" void kernel_launch(void* const* d_in, const int* in_sizes, int n_in,
                              void* d_out, int out_size)
{
    const float* s0   = (const float*)d_in[0];       // [N,128]
    const int*   ei   = (const int*)d_in[1];         // [2,E] int32
    const float* ea0  = (const float*)d_in[2];       // [E,16]
    const float* lnw  = (const float*)d_in[4];       // [L,128]
    const float* lnb  = (const float*)d_in[5];       // [L,128]
    const float* eW1  = (const float*)d_in[6];       // [L,272,16]
    const float* eb1  = (const float*)d_in[7];       // [L,16]
    const float* eW2  = (const float*)d_in[8];       // [L,16,16]
    const float* eb2  = (const float*)d_in[9];       // [L,16]
    // batch / nW1 / nb1 / nW2 / nb2 are dead in the reference dataflow

    int n = in_sizes[0] / D_;
    int e = in_sizes[2] / ED_;
    int L = in_sizes[4] / D_;

    float* out    = (float*)d_out;
    float* s_buf  = out;                      // final s
    float* ea_buf = out + (size_t)n * D_;     // final edge_attr

    const int* src = ei;
    const int* dst = ei + e;

    // stage edge-MLP weights into constant memory (capturable D2D copies)
    void *pWC, *pW2, *pB1, *pB2;
    cudaGetSymbolAddress(&pWC, cWC);
    cudaGetSymbolAddress(&pW2, cW2);
    cudaGetSymbolAddress(&pB1, cB1);
    cudaGetSymbolAddress(&pB2, cB2);
    cudaMemcpy2DAsync(pWC, 1024, eW1 + 256 * 16, 272 * 16 * 4, 1024, L,
                      cudaMemcpyDeviceToDevice);
    cudaMemcpyAsync(pW2, eW2, (size_t)L * 256 * 4, cudaMemcpyDeviceToDevice);
    cudaMemcpyAsync(pB1, eb1, (size_t)L * 16 * 4, cudaMemcpyDeviceToDevice);
    cudaMemcpyAsync(pB2, eb2, (size_t)L * 16 * 4, cudaMemcpyDeviceToDevice);

    size_t shmem = (size_t)(L_MAX * 4224 + L_MAX * 256 + 24 * 1024) * 4;
    cudaFuncSetAttribute(ln_all_kernel,
                         cudaFuncAttributeMaxDynamicSharedMemorySize, (int)shmem);

    ln_all_kernel<<<148, 768, shmem>>>(s0, s_buf, lnw, lnb, eW1, n, L);

    int edge_blocks = (e + 255) / 256;
    for (int i = 0; i < L; ++i)
        edge_kernel<<<edge_blocks, 256>>>(
            src, dst,
            (i == 0) ? ea0 : ea_buf, ea_buf,
            i, e);
}

// round 9
// speedup vs baseline: 1.1712x; 1.1355x over previous
#include <cuda_runtime.h>

#define D_    128
#define ED_   16
#define N_MAX 100000
#define L_MAX 5

// per-layer per-node projections, layout [layer][node][16]
__device__ __align__(128) float g_p[(size_t)L_MAX * N_MAX * ED_];
__device__ __align__(128) float g_q[(size_t)L_MAX * N_MAX * ED_];

// edge-MLP weights packed as float pairs for fma.rn.f32x2
__constant__ __align__(16) ulonglong2 cWC[L_MAX][64];
__constant__ __align__(16) ulonglong2 cW2[L_MAX][64];
__constant__ __align__(16) unsigned long long cB1[L_MAX][8];
__constant__ __align__(16) unsigned long long cB2[L_MAX][8];

// ---- f32x2 packed helpers ----
__device__ __forceinline__ unsigned long long pk2(float a) {
    unsigned long long r; asm("mov.b64 %0, {%1, %1};" : "=l"(r) : "f"(a)); return r;
}
__device__ __forceinline__ float2 up2(unsigned long long v) {
    float2 r; asm("mov.b64 {%0, %1}, %2;" : "=f"(r.x), "=f"(r.y) : "l"(v)); return r;
}
__device__ __forceinline__ unsigned long long fma2(unsigned long long a,
                                                   unsigned long long b,
                                                   unsigned long long c) {
    unsigned long long d;
    asm("fma.rn.f32x2 %0, %1, %2, %3;" : "=l"(d) : "l"(a), "l"(b), "l"(c));
    return d;
}
__device__ __forceinline__ unsigned long long add2(unsigned long long a,
                                                   unsigned long long b) {
    unsigned long long d;
    asm("add.rn.f32x2 %0, %1, %2;" : "=l"(d) : "l"(a), "l"(b));
    return d;
}

// ---------------------------------------------------------------------------
// All L layers of LayerNorm + both 128->16 projections. 8 rows per warp,
// rows live in registers across layers. 512 threads/block -> 128-reg cap,
// no spills (768 threads capped regs at 85 and spilled the row tile).
// ---------------------------------------------------------------------------
#define LNW 16   // warps per block
__global__ __launch_bounds__(512) void ln_all_kernel(
    const float* __restrict__ s_in, float* __restrict__ s_out,
    const float* __restrict__ lnw, const float* __restrict__ lnb,
    const float* __restrict__ eW1 /* [L,272,16] */, int n, int L)
{
    extern __shared__ __align__(16) float sm[];
    float* wT     = sm;                       // [5][32*132] transposed Wa|Wb
    float* sLn    = wT + L_MAX * 4224;        // [5][256] lnw|lnb
    float* rowbuf = sLn + L_MAX * 256;        // [LNW warps][8*128]

    for (int l = 0; l < L; ++l) {
        const float* w1 = eW1 + (size_t)l * 272 * 16;
        float* wTl = wT + l * 4224;
        for (int idx = threadIdx.x; idx < 2048; idx += 512) {
            int k = idx >> 4, j = idx & 15;
            wTl[j * 132 + k]        = w1[idx];          // Wa
            wTl[(16 + j) * 132 + k] = w1[2048 + idx];   // Wb
        }
        for (int idx = threadIdx.x; idx < 128; idx += 512) {
            sLn[l * 256 + idx]       = lnw[l * 128 + idx];
            sLn[l * 256 + 128 + idx] = lnb[l * 128 + idx];
        }
    }
    __syncthreads();

    int warp = threadIdx.x >> 5, lane = threadIdx.x & 31;
    float* rb = rowbuf + warp * 1024;
    int j = lane & 15;
    int rowsel = (lane < 16) ? 0 : 16;
    float* dstbase = (lane < 16) ? g_p : g_q;

    int stride = gridDim.x * LNW * 8;
    for (int row0 = (blockIdx.x * LNW + warp) * 8; row0 < n; row0 += stride) {
        if (row0 + 8 <= n) {
            float4 v[8];
            #pragma unroll
            for (int r = 0; r < 8; ++r)
                v[r] = reinterpret_cast<const float4*>(s_in)[(size_t)(row0 + r) * 32 + lane];

            for (int l = 0; l < L; ++l) {
                const float4* lnp = reinterpret_cast<const float4*>(sLn + l * 256);
                float4 wv = lnp[lane], bv = lnp[32 + lane];

                float s1[8], s2[8];
                #pragma unroll
                for (int r = 0; r < 8; ++r) {
                    s1[r] = (v[r].x + v[r].y) + (v[r].z + v[r].w);
                    s2[r] = fmaf(v[r].x, v[r].x,
                            fmaf(v[r].y, v[r].y,
                            fmaf(v[r].z, v[r].z, v[r].w * v[r].w)));
                }
                #pragma unroll
                for (int o = 16; o; o >>= 1) {
                    #pragma unroll
                    for (int r = 0; r < 8; ++r) {
                        s1[r] += __shfl_xor_sync(0xffffffffu, s1[r], o);
                        s2[r] += __shfl_xor_sync(0xffffffffu, s2[r], o);
                    }
                }
                #pragma unroll
                for (int r = 0; r < 8; ++r) {
                    float mu = s1[r] * 0.0078125f;
                    float rstd = rsqrtf(fmaf(s2[r], 0.0078125f, -mu * mu) + 1e-5f);
                    v[r].x = (v[r].x - mu) * rstd * wv.x + bv.x;
                    v[r].y = (v[r].y - mu) * rstd * wv.y + bv.y;
                    v[r].z = (v[r].z - mu) * rstd * wv.z + bv.z;
                    v[r].w = (v[r].w - mu) * rstd * wv.w + bv.w;
                    reinterpret_cast<float4*>(rb + r * 128)[lane] = v[r];
                }
                __syncwarp();

                const ulonglong2* wrow =
                    reinterpret_cast<const ulonglong2*>(wT + l * 4224 + (rowsel + j) * 132);
                unsigned long long acc[8] = {0,0,0,0,0,0,0,0};
                #pragma unroll
                for (int c = 0; c < 32; ++c) {
                    ulonglong2 wv2 = wrow[c];
                    #pragma unroll
                    for (int r = 0; r < 8; ++r) {
                        ulonglong2 rv = reinterpret_cast<const ulonglong2*>(rb + r * 128)[c];
                        acc[r] = fma2(rv.x, wv2.x, acc[r]);
                        acc[r] = fma2(rv.y, wv2.y, acc[r]);
                    }
                }
                #pragma unroll
                for (int r = 0; r < 8; ++r) {
                    float2 a = up2(acc[r]);
                    dstbase[((size_t)l * N_MAX + (row0 + r)) * 16 + j] = a.x + a.y;
                }
                __syncwarp();
            }

            #pragma unroll
            for (int r = 0; r < 8; ++r)
                reinterpret_cast<float4*>(s_out)[(size_t)(row0 + r) * 32 + lane] = v[r];
        } else {
            int nr = n - row0;
            for (int r = 0; r < nr; ++r) {
                float4 v = reinterpret_cast<const float4*>(s_in)[(size_t)(row0 + r) * 32 + lane];
                for (int l = 0; l < L; ++l) {
                    const float4* lnp = reinterpret_cast<const float4*>(sLn + l * 256);
                    float4 wv = lnp[lane], bv = lnp[32 + lane];
                    float s1 = (v.x + v.y) + (v.z + v.w);
                    float s2 = fmaf(v.x, v.x, fmaf(v.y, v.y, fmaf(v.z, v.z, v.w * v.w)));
                    #pragma unroll
                    for (int o = 16; o; o >>= 1) {
                        s1 += __shfl_xor_sync(0xffffffffu, s1, o);
                        s2 += __shfl_xor_sync(0xffffffffu, s2, o);
                    }
                    float mu = s1 * 0.0078125f;
                    float rstd = rsqrtf(fmaf(s2, 0.0078125f, -mu * mu) + 1e-5f);
                    v.x = (v.x - mu) * rstd * wv.x + bv.x;
                    v.y = (v.y - mu) * rstd * wv.y + bv.y;
                    v.z = (v.z - mu) * rstd * wv.z + bv.z;
                    v.w = (v.w - mu) * rstd * wv.w + bv.w;
                    reinterpret_cast<float4*>(rb)[lane] = v;
                    __syncwarp();
                    const ulonglong2* wrow =
                        reinterpret_cast<const ulonglong2*>(wT + l * 4224 + (rowsel + j) * 132);
                    unsigned long long a0 = 0ull, a1 = 0ull;
                    #pragma unroll
                    for (int c = 0; c < 32; c += 2) {
                        ulonglong2 w0 = wrow[c], w1v = wrow[c + 1];
                        ulonglong2 r0 = reinterpret_cast<const ulonglong2*>(rb)[c];
                        ulonglong2 r1 = reinterpret_cast<const ulonglong2*>(rb)[c + 1];
                        a0 = fma2(r0.x, w0.x,  a0);
                        a0 = fma2(r0.y, w0.y,  a0);
                        a1 = fma2(r1.x, w1v.x, a1);
                        a1 = fma2(r1.y, w1v.y, a1);
                    }
                    float2 f0 = up2(a0), f1 = up2(a1);
                    dstbase[((size_t)l * N_MAX + (row0 + r)) * 16 + j] =
                        (f0.x + f0.y) + (f1.x + f1.y);
                    __syncwarp();
                }
                reinterpret_cast<float4*>(s_out)[(size_t)(row0 + r) * 32 + lane] = v;
            }
        }
    }
}

// ---------------------------------------------------------------------------
// One thread per edge, one layer per launch (R6 proven-best shape):
// direct LDG.128 gathers, constant-port weights, 8 f32x2 accumulators.
// ---------------------------------------------------------------------------
__global__ __launch_bounds__(256) void edge_kernel(
    const int* __restrict__ src, const int* __restrict__ dst,
    const float* __restrict__ ea_in, float* __restrict__ ea_out,
    int layer, int e_total)
{
    int e = blockIdx.x * 256 + threadIdx.x;
    if (e >= e_total) return;

    int si = src[e], di = dst[e];
    const ulonglong2* P =
        reinterpret_cast<const ulonglong2*>(g_p + ((size_t)layer * N_MAX + si) * 16);
    const ulonglong2* Q =
        reinterpret_cast<const ulonglong2*>(g_q + ((size_t)layer * N_MAX + di) * 16);

    unsigned long long h[8];
    #pragma unroll
    for (int i = 0; i < 4; ++i) {
        ulonglong2 pv = P[i], qv = Q[i];
        h[2*i+0] = add2(add2(pv.x, qv.x), cB1[layer][2*i+0]);
        h[2*i+1] = add2(add2(pv.y, qv.y), cB1[layer][2*i+1]);
    }

    const float4* EA = reinterpret_cast<const float4*>(ea_in + (size_t)e * 16);
    #pragma unroll
    for (int c = 0; c < 4; ++c) {
        float4 ev = EA[c];
        float es[4] = {ev.x, ev.y, ev.z, ev.w};
        #pragma unroll
        for (int kk = 0; kk < 4; ++kk) {
            int k = c * 4 + kk;
            unsigned long long ek = pk2(es[kk]);
            ulonglong2 w0 = cWC[layer][k*4+0], w1 = cWC[layer][k*4+1];
            ulonglong2 w2v = cWC[layer][k*4+2], w3 = cWC[layer][k*4+3];
            h[0] = fma2(ek, w0.x,  h[0]);  h[1] = fma2(ek, w0.y,  h[1]);
            h[2] = fma2(ek, w1.x,  h[2]);  h[3] = fma2(ek, w1.y,  h[3]);
            h[4] = fma2(ek, w2v.x, h[4]);  h[5] = fma2(ek, w2v.y, h[5]);
            h[6] = fma2(ek, w3.x,  h[6]);  h[7] = fma2(ek, w3.y,  h[7]);
        }
    }

    float z[16];
    #pragma unroll
    for (int i = 0; i < 8; ++i) {
        float2 hv = up2(h[i]);
        z[2*i]   = __fdividef(hv.x, 1.0f + __expf(-hv.x));   // silu
        z[2*i+1] = __fdividef(hv.y, 1.0f + __expf(-hv.y));
    }

    unsigned long long o[8];
    #pragma unroll
    for (int i = 0; i < 8; ++i) o[i] = cB2[layer][i];
    #pragma unroll
    for (int k = 0; k < 16; ++k) {
        unsigned long long zk = pk2(z[k]);
        ulonglong2 w0 = cW2[layer][k*4+0], w1 = cW2[layer][k*4+1];
        ulonglong2 w2v = cW2[layer][k*4+2], w3 = cW2[layer][k*4+3];
        o[0] = fma2(zk, w0.x,  o[0]);  o[1] = fma2(zk, w0.y,  o[1]);
        o[2] = fma2(zk, w1.x,  o[2]);  o[3] = fma2(zk, w1.y,  o[3]);
        o[4] = fma2(zk, w2v.x, o[4]);  o[5] = fma2(zk, w2v.y, o[5]);
        o[6] = fma2(zk, w3.x,  o[6]);  o[7] = fma2(zk, w3.y,  o[7]);
    }

    ulonglong2* OUT = reinterpret_cast<ulonglong2*>(ea_out + (size_t)e * 16);
    #pragma unroll
    for (int i = 0; i < 4; ++i)
        OUT[i] = make_ulonglong2(o[2*i], o[2*i+1]);
}

extern "C" void kernel_launch(void* const* d_in, const int* in_sizes, int n_in,
                              void* d_out, int out_size)
{
    const float* s0   = (const float*)d_in[0];       // [N,128]
    const int*   ei   = (const int*)d_in[1];         // [2,E] int32
    const float* ea0  = (const float*)d_in[2];       // [E,16]
    const float* lnw  = (const float*)d_in[4];       // [L,128]
    const float* lnb  = (const float*)d_in[5];       // [L,128]
    const float* eW1  = (const float*)d_in[6];       // [L,272,16]
    const float* eb1  = (const float*)d_in[7];       // [L,16]
    const float* eW2  = (const float*)d_in[8];       // [L,16,16]
    const float* eb2  = (const float*)d_in[9];       // [L,16]
    // batch / nW1 / nb1 / nW2 / nb2 are dead in the reference dataflow

    int n = in_sizes[0] / D_;
    int e = in_sizes[2] / ED_;
    int L = in_sizes[4] / D_;

    float* out    = (float*)d_out;
    float* s_buf  = out;                      // final s
    float* ea_buf = out + (size_t)n * D_;     // final edge_attr

    const int* src = ei;
    const int* dst = ei + e;

    // stage edge-MLP weights into constant memory (capturable D2D copies)
    void *pWC, *pW2, *pB1, *pB2;
    cudaGetSymbolAddress(&pWC, cWC);
    cudaGetSymbolAddress(&pW2, cW2);
    cudaGetSymbolAddress(&pB1, cB1);
    cudaGetSymbolAddress(&pB2, cB2);
    cudaMemcpy2DAsync(pWC, 1024, eW1 + 256 * 16, 272 * 16 * 4, 1024, L,
                      cudaMemcpyDeviceToDevice);
    cudaMemcpyAsync(pW2, eW2, (size_t)L * 256 * 4, cudaMemcpyDeviceToDevice);
    cudaMemcpyAsync(pB1, eb1, (size_t)L * 16 * 4, cudaMemcpyDeviceToDevice);
    cudaMemcpyAsync(pB2, eb2, (size_t)L * 16 * 4, cudaMemcpyDeviceToDevice);

    size_t shmem = (size_t)(L_MAX * 4224 + L_MAX * 256 + LNW * 1024) * 4;
    cudaFuncSetAttribute(ln_all_kernel,
                         cudaFuncAttributeMaxDynamicSharedMemorySize, (int)shmem);

    ln_all_kernel<<<148, 512, shmem>>>(s0, s_buf, lnw, lnb, eW1, n, L);

    int edge_blocks = (e + 255) / 256;
    for (int i = 0; i < L; ++i)
        edge_kernel<<<edge_blocks, 256>>>(
            src, dst,
            (i == 0) ? ea0 : ea_buf, ea_buf,
            i, e);
}